// round 17
// baseline (speedup 1.0000x reference)
#include <cuda_runtime.h>
#include <math.h>

// Problem constants
#define NIMG 512          // B*C
#define NALL 1024         // pred + gt images

// Output offsets (tuple order, flattened)
#define OFF_E    0
#define OFF_U    524288
#define OFF_F    1048576
#define OFF_W    1572864
#define OFF_US   2097152
#define OFF_ES   2098176
#define OFF_ERR  2099200
#define OFF_CAL  2623488

// Global scratch
__device__ float g_T2[(size_t)NALL * 64 * 256];  // [img][c 0..63][row]; c<32: Tc, else Ts
__device__ float g_modes[(size_t)NALL * 2048];   // per image: [re 0..1023 | im 0..1023]

// ---------------------------------------------------------------------------
// Packed fp32x2 helpers (base sm_100 ISA; SASS FFMA2).
// Pair convention: lo = cos-side, hi = sin-side.
// ---------------------------------------------------------------------------
typedef unsigned long long u64p;
static __device__ __forceinline__ u64p pk2(float x, float y) {
    u64p r; asm("mov.b64 %0, {%1, %2};" : "=l"(r) : "f"(x), "f"(y)); return r;
}
static __device__ __forceinline__ u64p dup2(float x) {
    u64p r; asm("mov.b64 %0, {%1, %1};" : "=l"(r) : "f"(x)); return r;
}
static __device__ __forceinline__ void unpk2(u64p p, float& x, float& y) {
    asm("mov.b64 {%0, %1}, %2;" : "=f"(x), "=f"(y) : "l"(p));
}
static __device__ __forceinline__ u64p fma2(u64p a, u64p b, u64p c) {
    u64p d; asm("fma.rn.f32x2 %0, %1, %2, %3;" : "=l"(d) : "l"(a), "l"(b), "l"(c));
    return d;
}

// ---------------------------------------------------------------------------
// Interleaved twiddle table generator: 4096 floats at sm[tw+...]:
//   pair index pi = (P*64 + n)*16 + j ; float[2*pi] = cos(2pi n(2j+P)/256),
//   float[2*pi+1] = sin(...).  Warp-uniform broadcast reads in compute.
// ---------------------------------------------------------------------------
static __device__ __forceinline__ void gen_tw(float* sm, int tw, int tid, int nthr)
{
    for (int i = tid; i < 4096; i += nthr) {
        int pi = i >> 1;
        int j = pi & 15, n = (pi >> 4) & 63, p = pi >> 10;
        int m = (n * (2 * j + p)) & 255;
        float x = (float)m * (1.0f / 128.0f);
        sm[tw + i] = (i & 1) ? sinpif(x) : cospif(x);
    }
}

// ===========================================================================
// Stage A kernel: row DFT.  Interleaved (cos-data, sin-data) pairs + packed
// twiddles -> per n: 1 LDS.64 + 2 LDS.128 + 4 fma2 (7 issues).
// smem = 50688 B -> 4 CTAs/SM (32 warps).
// ===========================================================================
#define FE_OFF 0                 // P=0 pairs (CE,SE): 64*33*2 = 4224 floats
#define FO_OFF 4224              // P=1 pairs (CO,SO)
#define BD_OFF 8448              // boundaries: x0, x128, u64, v64 [4][32]
#define TWA    8576              // 4096 floats
#define A_FLOATS 12672           // 50688 B

static __device__ __forceinline__ void stA_comp(const float* sm, float* gdst,
                                                int lane, int q, int P, int JG)
{
    const float* fd = sm + (P ? FO_OFF : FE_OFF);
    const u64p* tw = (const u64p*)(sm + TWA) + (P * 1024 + JG * 4);
    u64p acc0 = 0, acc1 = 0, acc2 = 0, acc3 = 0;   // (aC_j, aS_j) pairs

#pragma unroll 7
    for (int n = 1; n < 64; n++) {
        u64p dv = *(const u64p*)(fd + (n * 33 + lane) * 2);   // (cu, sv)
        ulonglong2 t0 = *(const ulonglong2*)(tw + n * 16);
        ulonglong2 t1 = *(const ulonglong2*)(tw + n * 16 + 2);
        acc0 = fma2(dv, t0.x, acc0);
        acc1 = fma2(dv, t0.y, acc1);
        acc2 = fma2(dv, t1.x, acc2);
        acc3 = fma2(dv, t1.y, acc3);
    }
    float x0 = sm[BD_OFF + lane], x128 = sm[BD_OFF + 32 + lane];
    float u64v = sm[BD_OFF + 64 + lane], v64v = sm[BD_OFF + 96 + lane];
    const int row = q * 32 + lane;
    u64p accs[4] = {acc0, acc1, acc2, acc3};
#pragma unroll
    for (int jj = 0; jj < 4; jj++) {
        float c, s;
        unpk2(accs[jj], c, s);
        int j = JG * 4 + jj;
        float sgn = (j & 1) ? -1.f : 1.f;
        if (P == 0) {
            c += x0 + x128 + sgn * u64v;      // sin side: n=0,64 terms vanish
        } else {
            c += x0 - x128;
            s += sgn * v64v;
        }
        int k = 2 * j + P;
        gdst[k * 256 + row]        = c;       // coalesced: lanes = rows
        gdst[(32 + k) * 256 + row] = s;
    }
}

__global__ __launch_bounds__(256, 4) void k_stA(const float* __restrict__ pred,
                                                const float* __restrict__ gt)
{
    extern __shared__ float sm[];
    const int img = blockIdx.x;
    const float* src = (img < NIMG) ? pred + (size_t)img * 65536
                                    : gt   + (size_t)(img - NIMG) * 65536;
    float* gdst = g_T2 + (size_t)img * 16384;
    const int tid   = threadIdx.x;
    const int wid   = tid >> 5;
    const int lane  = tid & 31;
    const int n     = tid & 63;
    const int rbase = tid >> 6;
    const int P     = wid & 1;
    const int JG    = wid >> 1;

    gen_tw(sm, TWA, tid, 256);

#pragma unroll 1
    for (int q = 0; q < 8; q++) {
        if (q) __syncthreads();          // prior compute done -> fold buffers free
        const float* rows = src + q * 32 * 256;
#pragma unroll
        for (int it = 0; it < 8; it++) {
            const int r = rbase + it * 4;
            const float* row = rows + r * 256;
            if (n == 0) {
                sm[BD_OFF + r]      = row[0];
                sm[BD_OFF + 32 + r] = row[128];
                float a = row[64], b = row[192];
                sm[BD_OFF + 64 + r] = a + b;
                sm[BD_OFF + 96 + r] = a - b;
            } else {
                float a = row[n], b = row[256 - n], e = row[128 - n], d = row[128 + n];
                float u1 = a + b, u2 = e + d, v1 = a - b, v2 = e - d;
                *(u64p*)(sm + FE_OFF + (n * 33 + r) * 2) = pk2(u1 + u2, v1 - v2);
                *(u64p*)(sm + FO_OFF + (n * 33 + r) * 2) = pk2(u1 - u2, v1 + v2);
            }
        }
        __syncthreads();                 // fold + (q==0) tables visible
        stA_comp(sm, gdst, lane, q, P, JG);
    }
}

// ===========================================================================
// Stage B kernel: column DFT.  Same packing; 512 threads, 2 CTAs/SM.
// ===========================================================================
#define BPE   0                  // P=0 pairs: 63*65*2 = 8190 floats
#define BPO   8190
#define B_SP  16380              // [4][64] specials: col 0,64,128,192
#define TWB   16636              // 4096 floats
#define B_FLOATS 20732           // 82928 B
#define B_RA  0                  // results reuse fold area after sync
#define B_RB  2112

static __device__ __forceinline__ void stB_comp(const float* sm, int c, int P, int JH,
                                                float (&aA)[4], float (&aB)[4])
{
    const float* fd = sm + (P ? BPO : BPE);
    const u64p* tw = (const u64p*)(sm + TWB) + (P * 1024 + JH * 4);
    u64p acc0 = 0, acc1 = 0, acc2 = 0, acc3 = 0;

#pragma unroll 7
    for (int nn = 1; nn < 64; nn++) {
        u64p dv = *(const u64p*)(fd + ((nn - 1) * 65 + c) * 2);   // (cs, ss)
        ulonglong2 t0 = *(const ulonglong2*)(tw + nn * 16);
        ulonglong2 t1 = *(const ulonglong2*)(tw + nn * 16 + 2);
        acc0 = fma2(dv, t0.x, acc0);
        acc1 = fma2(dv, t0.y, acc1);
        acc2 = fma2(dv, t1.x, acc2);
        acc3 = fma2(dv, t1.y, acc3);
    }
    float s0   = sm[B_SP + c];
    float s64  = sm[B_SP + 64 + c];
    float s128 = sm[B_SP + 128 + c];
    float s192 = sm[B_SP + 192 + c];
    u64p accs[4] = {acc0, acc1, acc2, acc3};
#pragma unroll
    for (int jj = 0; jj < 4; jj++) {
        float A, Bv;
        unpk2(accs[jj], A, Bv);
        int j = JH * 4 + jj;
        float sgn = (j & 1) ? -1.f : 1.f;
        if (P == 0) {
            A += s0 + s128 + sgn * (s64 + s192);
        } else {
            A += s0 - s128;
            Bv += sgn * (s64 - s192);
        }
        aA[jj] = A;
        aB[jj] = Bv;
    }
}

__global__ __launch_bounds__(512, 2) void k_stB()
{
    extern __shared__ float sm[];
    const int img = blockIdx.x;
    const int tid = threadIdx.x;
    const int wid = tid >> 5, lane = tid & 31;
    const float* base = g_T2 + (size_t)img * 16384;

    gen_tw(sm, TWB, tid, 512);

    // Fold-on-load: lanes sweep n within a column (coalesced LDG);
    // paired STS.64 (2-phase conflict-free).
    {
        const int n  = tid & 63;
        const int cg = tid >> 6;             // 0..7
#pragma unroll 1
        for (int itc = 0; itc < 8; itc++) {
            const int c = cg + itc * 8;
            const float* col = base + c * 256;
            if (n == 0) {
                sm[B_SP + c]       = col[0];
                sm[B_SP + 64 + c]  = col[64];
                sm[B_SP + 128 + c] = col[128];
                sm[B_SP + 192 + c] = col[192];
            } else {
                float a = col[n], b = col[256 - n], e = col[128 - n], d = col[128 + n];
                *(u64p*)(sm + BPE + ((n - 1) * 65 + c) * 2) =
                    pk2((a + b) + (e + d), (a - b) - (e - d));
                *(u64p*)(sm + BPO + ((n - 1) * 65 + c) * 2) =
                    pk2((a + b) - (e + d), (a - b) + (e - d));
            }
        }
    }
    __syncthreads();

    // Compute: 16 warps = (c-half, P, JH); 4 k per thread.
    const int c   = lane + (wid >> 3) * 32;
    const int sub = wid & 7;
    const int P   = sub & 1;
    const int JH  = sub >> 1;
    float aA[4], aB[4];
    stB_comp(sm, c, P, JH, aA, aB);
    __syncthreads();                         // fold-array reads complete

#pragma unroll
    for (int jj = 0; jj < 4; jj++) {
        const int k = 2 * (JH * 4 + jj) + P;
        sm[B_RA + c * 33 + k] = aA[jj];
        sm[B_RB + c * 33 + k] = aB[jj];
    }
    __syncthreads();

    // Combine into complex modes; coalesced writes.
    float* mp = g_modes + (size_t)img * 2048;
#pragma unroll
    for (int t = 0; t < 2; t++) {
        int idx = tid + t * 512;
        int k1 = idx >> 5, k2 = idx & 31;
        float ATc = sm[B_RA + k2 * 33 + k1];
        float ATs = sm[B_RA + (32 + k2) * 33 + k1];
        float BTc = sm[B_RB + k2 * 33 + k1];
        float BTs = sm[B_RB + (32 + k2) * 33 + k1];
        mp[idx]        = ATc - BTs;
        mp[1024 + idx] = -(BTc + ATs);
    }
}

// ===========================================================================
// K2: fused MLP + epilogue with f32x2 packing (R13/R16-passing, unchanged).
// ===========================================================================
__global__ __launch_bounds__(256) void k_mlp_epi(const float* __restrict__ W1,
                                                 const float* __restrict__ b1,
                                                 const float* __restrict__ W2,
                                                 const float* __restrict__ b2,
                                                 const float* __restrict__ W3,
                                                 const float* __restrict__ b3,
                                                 float* __restrict__ out)
{
    __shared__ float sW1[128], sb1[64], sb2[32], sW3[32], sb3v;
    __shared__ __align__(16) float sW2[2048];
    __shared__ float sRed[256];
    __shared__ float sTe;
    const int tid = threadIdx.x;
    const int img = blockIdx.x;

    for (int i = tid; i < 128;  i += 256) sW1[i] = W1[i];
    for (int i = tid; i < 2048; i += 256) sW2[i] = W2[i];
    if (tid < 64) sb1[tid] = b1[tid];
    if (tid < 32) { sb2[tid] = b2[tid]; sW3[tid] = W3[tid]; }
    if (tid == 0) sb3v = b3[0];
    __syncthreads();

    const float* mp = g_modes + (size_t)img * 2048;
    const float* mg = g_modes + (size_t)(NIMG + img) * 2048;
    const int base = img * 1024;

    float ev[4], uv[4];
    float eSum = 0.f;

#pragma unroll 1
    for (int bi = 0; bi < 2; bi++) {
        const int i0 = tid + bi * 512;
        const int i1 = i0 + 256;
        float pr0 = mp[i0], pi0 = mp[1024 + i0];
        float pr1 = mp[i1], pi1 = mp[1024 + i1];
        float gr0 = mg[i0], gi0 = mg[1024 + i0];
        float gr1 = mg[i1], gi1 = mg[1024 + i1];

        float E0 = fmaf(pr0, pr0, pi0 * pi0);
        float E1 = fmaf(pr1, pr1, pi1 * pi1);
        out[OFF_E + base + i0] = E0;
        out[OFF_E + base + i1] = E1;
        float d0r = pr0 - gr0, d0i = pi0 - gi0;
        float d1r = pr1 - gr1, d1i = pi1 - gi1;
        out[OFF_ERR + base + i0] = fmaf(d0r, d0r, d0i * d0i);
        out[OFF_ERR + base + i1] = fmaf(d1r, d1r, d1i * d1i);
        ev[bi * 2] = E0; ev[bi * 2 + 1] = E1;
        eSum += E0 + E1;

        u64p h2a2[16], h2b2[16];
#pragma unroll
        for (int q = 0; q < 16; q++) {
            u64p b2p = pk2(sb2[2 * q], sb2[2 * q + 1]);
            h2a2[q] = b2p;
            h2b2[q] = b2p;
        }

#pragma unroll 8
        for (int i = 0; i < 64; i++) {
            float w1a = sW1[i], w1b = sW1[64 + i], bb = sb1[i];
            float a0 = fmaf(pr0, w1a, fmaf(pi0, w1b, bb));
            float a1 = fmaf(pr1, w1a, fmaf(pi1, w1b, bb));
            a0 = a0 > 0.f ? a0 : 0.f;
            a1 = a1 > 0.f ? a1 : 0.f;
            u64p a0p = dup2(a0);
            u64p a1p = dup2(a1);
            const ulonglong2* w2p = (const ulonglong2*)(sW2 + i * 32);
#pragma unroll
            for (int q = 0; q < 8; q++) {
                ulonglong2 wp = w2p[q];
                h2a2[2*q]   = fma2(a0p, wp.x, h2a2[2*q]);
                h2a2[2*q+1] = fma2(a0p, wp.y, h2a2[2*q+1]);
                h2b2[2*q]   = fma2(a1p, wp.x, h2b2[2*q]);
                h2b2[2*q+1] = fma2(a1p, wp.y, h2b2[2*q+1]);
            }
        }
        float o0 = sb3v, o1 = sb3v;
#pragma unroll
        for (int q = 0; q < 16; q++) {
            float xa, ya, xb, yb;
            unpk2(h2a2[q], xa, ya);
            unpk2(h2b2[q], xb, yb);
            float w3x = sW3[2 * q], w3y = sW3[2 * q + 1];
            o0 = fmaf(xa > 0.f ? xa : 0.f, w3x, o0);
            o0 = fmaf(ya > 0.f ? ya : 0.f, w3y, o0);
            o1 = fmaf(xb > 0.f ? xb : 0.f, w3x, o1);
            o1 = fmaf(yb > 0.f ? yb : 0.f, w3y, o1);
        }
        float u0 = fmaxf(o0, 0.f) + log1pf(expf(-fabsf(o0)));
        float u1 = fmaxf(o1, 0.f) + log1pf(expf(-fabsf(o1)));
        out[OFF_U + base + i0] = u0;
        out[OFF_U + base + i1] = u1;
        uv[bi * 2] = u0; uv[bi * 2 + 1] = u1;
    }

    sRed[tid] = eSum;
    __syncthreads();
    for (int w = 128; w > 0; w >>= 1) {
        if (tid < w) sRed[tid] += sRed[tid + w];
        __syncthreads();
    }
    if (tid == 0) sTe = sRed[0];
    __syncthreads();
    const float te = sTe + 1e-8f;

#pragma unroll
    for (int b = 0; b < 4; b++) {
        int idx = tid + b * 256;
        float F = ev[b] / te;
        out[OFF_F + base + idx] = F;
        out[OFF_W + base + idx] = F * uv[b];
    }
}

// ===========================================================================
// K3: per-mode stats (unchanged, known-good).
// ===========================================================================
__global__ __launch_bounds__(256) void k_stats(float* __restrict__ out)
{
    __shared__ double red[6][256];
    const int tid = threadIdx.x;
    const int kl  = tid & 7;
    const int sg  = tid >> 3;                 // 0..31
    const int k   = blockIdx.x * 8 + kl;

    double su = 0, se = 0, sen = 0, sue = 0, suu = 0, see = 0;
    for (int s = sg; s < NIMG; s += 32) {
        float u  = out[OFF_U   + (size_t)s * 1024 + k];
        float e  = out[OFF_ERR + (size_t)s * 1024 + k];
        float en = out[OFF_E   + (size_t)s * 1024 + k];
        su += u; se += e; sen += en;
        sue += (double)u * (double)e;
        suu += (double)u * (double)u;
        see += (double)e * (double)e;
    }
    red[0][tid] = su;  red[1][tid] = se;  red[2][tid] = sen;
    red[3][tid] = sue; red[4][tid] = suu; red[5][tid] = see;
    __syncthreads();

    for (int off = 16; off >= 1; off >>= 1) {
        if (sg < off) {
#pragma unroll
            for (int m = 0; m < 6; m++)
                red[m][tid] += red[m][tid + off * 8];
        }
        __syncthreads();
    }
    if (tid < 8) {
        double tsu = red[0][tid], tse = red[1][tid], tsen = red[2][tid];
        double tsue = red[3][tid], tsuu = red[4][tid], tsee = red[5][tid];
        out[OFF_US + k] = (float)(tsu  * (1.0 / 512.0));
        out[OFF_ES + k] = (float)(tsen * (1.0 / 512.0));
        double num  = tsue - tsu * tse * (1.0 / 512.0);
        double varu = tsuu - tsu * tsu * (1.0 / 512.0);
        double vare = tsee - tse * tse * (1.0 / 512.0);
        out[OFF_CAL + k] = (float)(num / (sqrt(varu * vare) + 1e-8));
    }
}

// ---------------------------------------------------------------------------
extern "C" void kernel_launch(void* const* d_in, const int* in_sizes, int n_in,
                              void* d_out, int out_size)
{
    const float* pred = (const float*)d_in[0];
    // d_in[1] = uncertainty: unused by the reference
    const float* gt   = (const float*)d_in[2];
    const float* W1   = (const float*)d_in[3];
    const float* b1   = (const float*)d_in[4];
    const float* W2   = (const float*)d_in[5];
    const float* b2   = (const float*)d_in[6];
    const float* W3   = (const float*)d_in[7];
    const float* b3   = (const float*)d_in[8];
    float* out = (float*)d_out;

    const int smemA = A_FLOATS * 4;   // 50688 B
    const int smemB = B_FLOATS * 4;   // 82928 B
    cudaFuncSetAttribute(k_stA, cudaFuncAttributeMaxDynamicSharedMemorySize, smemA);
    cudaFuncSetAttribute(k_stB, cudaFuncAttributeMaxDynamicSharedMemorySize, smemB);

    k_stA<<<1024, 256, smemA>>>(pred, gt);
    k_stB<<<1024, 512, smemB>>>();
    k_mlp_epi<<<512, 256>>>(W1, b1, W2, b2, W3, b3, out);
    k_stats<<<128, 256>>>(out);
}